// round 1
// baseline (speedup 1.0000x reference)
#include <cuda_runtime.h>
#include <cstdint>
#include <cstddef>

#define EMBED 1024
#define HEADS 16
#define DHEAD 64
#define NBATCH 4
#define LSEQ 2048
#define MROWS (NBATCH * LSEQ)   // 8192

// ---------------- scratch (static device globals; no allocation) ----------------
__device__ float g_qp[(size_t)MROWS * EMBED];
__device__ float g_kp[(size_t)MROWS * EMBED];
__device__ float g_vp[(size_t)MROWS * EMBED];
__device__ float g_ao[(size_t)MROWS * EMBED];

// ---------------- helpers ----------------
__device__ __forceinline__ unsigned f2tf(float x) {
    unsigned u;
    asm("cvt.rna.tf32.f32 %0, %1;" : "=r"(u) : "f"(x));
    return u;
}
__device__ __forceinline__ float tf32r(float x) { return __uint_as_float(f2tf(x)); }

__device__ __forceinline__ void mma8(float* c, const unsigned* a, const unsigned* b) {
    asm volatile(
        "mma.sync.aligned.m16n8k8.row.col.f32.tf32.tf32.f32 "
        "{%0,%1,%2,%3}, {%4,%5,%6,%7}, {%8,%9}, {%0,%1,%2,%3};"
        : "+f"(c[0]), "+f"(c[1]), "+f"(c[2]), "+f"(c[3])
        : "r"(a[0]), "r"(a[1]), "r"(a[2]), "r"(a[3]), "r"(b[0]), "r"(b[1]));
}

__device__ __forceinline__ void cp16(void* sdst, const void* gsrc) {
    unsigned s = (unsigned)__cvta_generic_to_shared(sdst);
    asm volatile("cp.async.cg.shared.global [%0], [%1], 16;" :: "r"(s), "l"(gsrc));
}
__device__ __forceinline__ void cp_commit() { asm volatile("cp.async.commit_group;"); }
__device__ __forceinline__ void cp_wait1()  { asm volatile("cp.async.wait_group 1;"); }

// ================================================================
// GEMM: C[M,N] = A[M,K] @ W[N,K]^T + bias[N]
// tf32 mma.sync, BM=BN=128, BK=32, 256 threads (8 warps, warp tile 32x64)
// cp.async double buffered. roundOut: round result to tf32 (for q/k/v proj).
// Requires M%128==0, N%128==0, K%32==0.
// ================================================================
#define GLD 36

__global__ __launch_bounds__(256, 2)
void gemm_tf32(const float* __restrict__ A, const float* __restrict__ W,
               const float* __restrict__ bias, float* __restrict__ C,
               int M, int N, int K, int roundOut)
{
    extern __shared__ float sm[];
    float* sA = sm;                    // 2 bufs x 128 x 36
    float* sB = sm + 2 * 128 * GLD;    // 2 bufs x 128 x 36

    const int tid = threadIdx.x;
    const int lane = tid & 31, wid = tid >> 5;
    const int wm = wid & 3, wn = wid >> 2;       // 4 x 2 warps
    const int bm = blockIdx.y * 128, bn = blockIdx.x * 128;
    const int nk = K >> 5;

    float acc[2][8][4];
#pragma unroll
    for (int i = 0; i < 2; i++)
#pragma unroll
        for (int j = 0; j < 8; j++)
#pragma unroll
            for (int t = 0; t < 4; t++) acc[i][j][t] = 0.f;

    auto issue = [&](int kt, int buf) {
        const float* Ag = A + (size_t)bm * K + kt * 32;
        const float* Wg = W + (size_t)bn * K + kt * 32;
        float* sa = sA + buf * 128 * GLD;
        float* sb = sB + buf * 128 * GLD;
#pragma unroll
        for (int i = 0; i < 4; i++) {
            int idx = tid + i * 256;
            int r = idx >> 3, q = idx & 7;
            cp16(sa + r * GLD + q * 4, Ag + (size_t)r * K + q * 4);
        }
#pragma unroll
        for (int i = 0; i < 4; i++) {
            int idx = tid + i * 256;
            int r = idx >> 3, q = idx & 7;
            cp16(sb + r * GLD + q * 4, Wg + (size_t)r * K + q * 4);
        }
    };

    issue(0, 0);
    cp_commit();

    for (int kt = 0; kt < nk; ++kt) {
        if (kt + 1 < nk) issue(kt + 1, (kt + 1) & 1);
        cp_commit();
        cp_wait1();
        __syncthreads();

        const float* sa = sA + (kt & 1) * 128 * GLD + (wm * 32) * GLD;
        const float* sb = sB + (kt & 1) * 128 * GLD + (wn * 64) * GLD;

#pragma unroll
        for (int kk = 0; kk < 4; kk++) {
            unsigned a[2][4], b[8][2];
            const int c0 = kk * 8 + (lane & 3);
            const int r0 = lane >> 2;
#pragma unroll
            for (int mt = 0; mt < 2; mt++) {
                const float* p = sa + (mt * 16 + r0) * GLD + c0;
                a[mt][0] = f2tf(p[0]);
                a[mt][1] = f2tf(p[8 * GLD]);
                a[mt][2] = f2tf(p[4]);
                a[mt][3] = f2tf(p[8 * GLD + 4]);
            }
#pragma unroll
            for (int nt = 0; nt < 8; nt++) {
                const float* p = sb + (nt * 8 + r0) * GLD + c0;
                b[nt][0] = f2tf(p[0]);
                b[nt][1] = f2tf(p[4]);
            }
#pragma unroll
            for (int mt = 0; mt < 2; mt++)
#pragma unroll
                for (int nt = 0; nt < 8; nt++) mma8(acc[mt][nt], a[mt], b[nt]);
        }
        __syncthreads();
    }

    // epilogue
#pragma unroll
    for (int mt = 0; mt < 2; mt++) {
        const int row = bm + wm * 32 + mt * 16 + (lane >> 2);
#pragma unroll
        for (int nt = 0; nt < 8; nt++) {
            const int col = bn + wn * 64 + nt * 8 + 2 * (lane & 3);
            const float b0 = bias[col], b1 = bias[col + 1];
            float v0 = acc[mt][nt][0] + b0, v1 = acc[mt][nt][1] + b1;
            float v2 = acc[mt][nt][2] + b0, v3 = acc[mt][nt][3] + b1;
            if (roundOut) { v0 = tf32r(v0); v1 = tf32r(v1); v2 = tf32r(v2); v3 = tf32r(v3); }
            C[(size_t)row * N + col]           = v0;
            C[(size_t)row * N + col + 1]       = v1;
            C[(size_t)(row + 8) * N + col]     = v2;
            C[(size_t)(row + 8) * N + col + 1] = v3;
        }
    }
}

// ================================================================
// Flash attention, tf32 mma. One CTA = 128 q-rows of one (n,h).
// qp/kp/vp are pre-rounded to tf32 (projection epilogue), so fragments
// are used bit-exact with no per-element cvt in the mainloop.
// scale = 1/sqrt(EMBED) = 1/32 (faithful to reference). Masks are no-ops.
// ================================================================
#define LQ 68
#define LK 68
#define LV 72
#define LP 132

__global__ __launch_bounds__(256, 1)
void attn_tf32(const float* __restrict__ qp, const float* __restrict__ kp,
               const float* __restrict__ vp, float* __restrict__ op)
{
    extern __shared__ float sm[];
    float* sQ  = sm;                 // 128 x 68
    float* sK  = sQ + 128 * LQ;      // 128 x 68
    float* sV  = sK + 128 * LK;      // 128 x 72
    float* sP  = sV + 128 * LV;      // 128 x 132
    float* sM  = sP + 128 * LP;      // 128
    float* sL  = sM + 128;           // 128
    float* sAl = sL + 128;           // 128

    const int tid = threadIdx.x, lane = tid & 31, wid = tid >> 5;
    const int wm = wid & 3, wn = wid >> 2;
    const int n = blockIdx.y >> 4, h = blockIdx.y & 15;
    const int q0 = blockIdx.x * 128;

    const size_t base = (size_t)n * LSEQ * EMBED + (size_t)h * DHEAD;

    // load Q tile once
#pragma unroll
    for (int i = 0; i < 8; i++) {
        int idx = tid + i * 256;
        int r = idx >> 4, q = idx & 15;
        float4 val = *(const float4*)(qp + base + (size_t)(q0 + r) * EMBED + q * 4);
        float* d = sQ + r * LQ + q * 4;
        d[0] = val.x; d[1] = val.y; d[2] = val.z; d[3] = val.w;
    }
    if (tid < 128) { sM[tid] = -1e30f; sL[tid] = 0.f; }

    float o[2][4][4];
#pragma unroll
    for (int a = 0; a < 2; a++)
#pragma unroll
        for (int b = 0; b < 4; b++)
#pragma unroll
            for (int c = 0; c < 4; c++) o[a][b][c] = 0.f;

    for (int kb = 0; kb < LSEQ / 128; ++kb) {
        __syncthreads();   // prev iter's sP/sV reads done; Q/stat init done
        // load K, V tiles
#pragma unroll
        for (int i = 0; i < 8; i++) {
            int idx = tid + i * 256;
            int r = idx >> 4, q = idx & 15;
            size_t g = base + (size_t)(kb * 128 + r) * EMBED + q * 4;
            float4 kv = *(const float4*)(kp + g);
            float* d = sK + r * LK + q * 4;
            d[0] = kv.x; d[1] = kv.y; d[2] = kv.z; d[3] = kv.w;
            float4 vv = *(const float4*)(vp + g);
            float* d2 = sV + r * LV + q * 4;
            d2[0] = vv.x; d2[1] = vv.y; d2[2] = vv.z; d2[3] = vv.w;
        }
        __syncthreads();

        // ---- S = Q K^T  (warp tile 32x64, k = 64) ----
        float s[2][8][4];
#pragma unroll
        for (int a = 0; a < 2; a++)
#pragma unroll
            for (int b = 0; b < 8; b++)
#pragma unroll
                for (int c = 0; c < 4; c++) s[a][b][c] = 0.f;
        {
            const float* q_ = sQ + (wm * 32) * LQ;
            const float* k_ = sK + (wn * 64) * LK;
#pragma unroll
            for (int kk = 0; kk < 8; kk++) {
                unsigned a[2][4], b[8][2];
                const int c0 = kk * 8 + (lane & 3);
                const int r0 = lane >> 2;
#pragma unroll
                for (int mt = 0; mt < 2; mt++) {
                    const float* p = q_ + (mt * 16 + r0) * LQ + c0;
                    a[mt][0] = __float_as_uint(p[0]);
                    a[mt][1] = __float_as_uint(p[8 * LQ]);
                    a[mt][2] = __float_as_uint(p[4]);
                    a[mt][3] = __float_as_uint(p[8 * LQ + 4]);
                }
#pragma unroll
                for (int nt = 0; nt < 8; nt++) {
                    const float* p = k_ + (nt * 8 + r0) * LK + c0;
                    b[nt][0] = __float_as_uint(p[0]);
                    b[nt][1] = __float_as_uint(p[4]);
                }
#pragma unroll
                for (int mt = 0; mt < 2; mt++)
#pragma unroll
                    for (int nt = 0; nt < 8; nt++) mma8(s[mt][nt], a[mt], b[nt]);
            }
        }
        // store S to shared P buffer
#pragma unroll
        for (int mt = 0; mt < 2; mt++) {
            const int r = wm * 32 + mt * 16 + (lane >> 2);
#pragma unroll
            for (int nt = 0; nt < 8; nt++) {
                const int c = wn * 64 + nt * 8 + 2 * (lane & 3);
                sP[r * LP + c]           = s[mt][nt][0];
                sP[r * LP + c + 1]       = s[mt][nt][1];
                sP[(r + 8) * LP + c]     = s[mt][nt][2];
                sP[(r + 8) * LP + c + 1] = s[mt][nt][3];
            }
        }
        __syncthreads();

        // ---- online softmax (one thread per q-row) ----
        if (tid < 128) {
            const float scale = 0.03125f;   // 1/sqrt(1024)
            float* row = sP + tid * LP;
            const float mprev = sM[tid];
            float mx = mprev;
#pragma unroll 4
            for (int j = 0; j < 128; j++) mx = fmaxf(mx, row[j] * scale);
            const float alpha = __expf(mprev - mx);
            float sum = 0.f;
#pragma unroll 4
            for (int j = 0; j < 128; j++) {
                float p = __expf(row[j] * scale - mx);
                sum += p;
                row[j] = tf32r(p);
            }
            sL[tid] = sL[tid] * alpha + sum;
            sM[tid] = mx;
            sAl[tid] = alpha;
        }
        __syncthreads();

        // ---- rescale O, then O += P V (warp tile 32x32, k = 128) ----
        {
#pragma unroll
            for (int mt = 0; mt < 2; mt++) {
                const int r = wm * 32 + mt * 16 + (lane >> 2);
                const float a0 = sAl[r], a1 = sAl[r + 8];
#pragma unroll
                for (int nt = 0; nt < 4; nt++) {
                    o[mt][nt][0] *= a0; o[mt][nt][1] *= a0;
                    o[mt][nt][2] *= a1; o[mt][nt][3] *= a1;
                }
            }
            const float* p_ = sP + (wm * 32) * LP;
            const float* v_ = sV + wn * 32;
#pragma unroll
            for (int kk = 0; kk < 16; kk++) {
                unsigned a[2][4], b[4][2];
                const int c0 = kk * 8 + (lane & 3);
                const int r0 = lane >> 2;
#pragma unroll
                for (int mt = 0; mt < 2; mt++) {
                    const float* p = p_ + (mt * 16 + r0) * LP + c0;
                    a[mt][0] = __float_as_uint(p[0]);
                    a[mt][1] = __float_as_uint(p[8 * LP]);
                    a[mt][2] = __float_as_uint(p[4]);
                    a[mt][3] = __float_as_uint(p[8 * LP + 4]);
                }
#pragma unroll
                for (int nt = 0; nt < 4; nt++) {
                    const float* pv = v_ + c0 * LV + nt * 8 + r0;
                    b[nt][0] = __float_as_uint(pv[0]);
                    b[nt][1] = __float_as_uint(pv[4 * LV]);
                }
#pragma unroll
                for (int mt = 0; mt < 2; mt++)
#pragma unroll
                    for (int nt = 0; nt < 4; nt++) mma8(o[mt][nt], a[mt], b[nt]);
            }
        }
    }

    // ---- epilogue: normalize, round to tf32, store ----
#pragma unroll
    for (int mt = 0; mt < 2; mt++) {
        const int r = wm * 32 + mt * 16 + (lane >> 2);
        const float inv0 = 1.f / sL[r], inv1 = 1.f / sL[r + 8];
#pragma unroll
        for (int nt = 0; nt < 4; nt++) {
            const int c = wn * 32 + nt * 8 + 2 * (lane & 3);
            const size_t g0 = base + (size_t)(q0 + r) * EMBED + c;
            const size_t g1 = base + (size_t)(q0 + r + 8) * EMBED + c;
            op[g0]     = tf32r(o[mt][nt][0] * inv0);
            op[g0 + 1] = tf32r(o[mt][nt][1] * inv0);
            op[g1]     = tf32r(o[mt][nt][2] * inv1);
            op[g1 + 1] = tf32r(o[mt][nt][3] * inv1);
        }
    }
}

// ================================================================
// launch
// ================================================================
extern "C" void kernel_launch(void* const* d_in, const int* in_sizes, int n_in,
                              void* d_out, int out_size)
{
    (void)in_sizes; (void)n_in; (void)out_size;
    const float* q  = (const float*)d_in[0];
    const float* k  = (const float*)d_in[1];
    const float* v  = (const float*)d_in[2];
    // d_in[3] padding_mask, d_in[4] sequence_mask: dead in reference
    const float* Wq = (const float*)d_in[5];
    const float* bq = (const float*)d_in[6];
    const float* Wk = (const float*)d_in[7];
    const float* bk = (const float*)d_in[8];
    const float* Wv = (const float*)d_in[9];
    const float* bv = (const float*)d_in[10];
    const float* Wo = (const float*)d_in[11];
    const float* bo = (const float*)d_in[12];
    float* out = (float*)d_out;

    float *qp, *kp, *vp, *ao;
    cudaGetSymbolAddress((void**)&qp, g_qp);
    cudaGetSymbolAddress((void**)&kp, g_kp);
    cudaGetSymbolAddress((void**)&vp, g_vp);
    cudaGetSymbolAddress((void**)&ao, g_ao);

    const int gemmSmem = 2 * 128 * GLD * 2 * (int)sizeof(float);   // 73728
    const int attnSmem = (128 * LQ + 128 * LK + 128 * LV + 128 * LP + 384)
                         * (int)sizeof(float);                      // 175616
    cudaFuncSetAttribute(gemm_tf32, cudaFuncAttributeMaxDynamicSharedMemorySize, gemmSmem);
    cudaFuncSetAttribute(attn_tf32, cudaFuncAttributeMaxDynamicSharedMemorySize, attnSmem);

    dim3 gg(EMBED / 128, MROWS / 128);   // (8, 64)
    dim3 ga(LSEQ / 128, NBATCH * HEADS); // (16, 64)

    gemm_tf32<<<gg, 256, gemmSmem>>>(q, Wq, bq, qp, MROWS, EMBED, EMBED, 1);
    gemm_tf32<<<gg, 256, gemmSmem>>>(k, Wk, bk, kp, MROWS, EMBED, EMBED, 1);
    gemm_tf32<<<gg, 256, gemmSmem>>>(v, Wv, bv, vp, MROWS, EMBED, EMBED, 1);
    attn_tf32<<<ga, 256, attnSmem>>>(qp, kp, vp, ao);
    gemm_tf32<<<gg, 256, gemmSmem>>>(ao, Wo, bo, out, MROWS, EMBED, EMBED, 0);
}

// round 2
// speedup vs baseline: 1.2946x; 1.2946x over previous
#include <cuda_runtime.h>
#include <cstdint>
#include <cstddef>

#define EMBED 1024
#define HEADS 16
#define DHEAD 64
#define NBATCH 4
#define LSEQ 2048
#define MROWS (NBATCH * LSEQ)   // 8192
#define NB (LSEQ / 128)         // 16

// ---------------- scratch (static device globals; no allocation) ----------------
__device__ float g_qp[(size_t)MROWS * EMBED];
__device__ float g_kp[(size_t)MROWS * EMBED];
__device__ float g_vp[(size_t)MROWS * EMBED];
__device__ float g_ao[(size_t)MROWS * EMBED];

// ---------------- helpers ----------------
__device__ __forceinline__ unsigned f2tf(float x) {
    unsigned u;
    asm("cvt.rna.tf32.f32 %0, %1;" : "=r"(u) : "f"(x));
    return u;
}
__device__ __forceinline__ float tf32r(float x) { return __uint_as_float(f2tf(x)); }

__device__ __forceinline__ void mma8(float* c, const unsigned* a, const unsigned* b) {
    asm volatile(
        "mma.sync.aligned.m16n8k8.row.col.f32.tf32.tf32.f32 "
        "{%0,%1,%2,%3}, {%4,%5,%6,%7}, {%8,%9}, {%0,%1,%2,%3};"
        : "+f"(c[0]), "+f"(c[1]), "+f"(c[2]), "+f"(c[3])
        : "r"(a[0]), "r"(a[1]), "r"(a[2]), "r"(a[3]), "r"(b[0]), "r"(b[1]));
}

__device__ __forceinline__ void cp16(void* sdst, const void* gsrc) {
    unsigned s = (unsigned)__cvta_generic_to_shared(sdst);
    asm volatile("cp.async.cg.shared.global [%0], [%1], 16;" :: "r"(s), "l"(gsrc));
}
__device__ __forceinline__ void cp_commit() { asm volatile("cp.async.commit_group;"); }

// ================================================================
// GEMM body: C[M,N] = A[M,K] @ W[N,K]^T + bias[N]  (M=8192,N=K=1024)
// tf32 mma.sync, BM=BN=128, BK=32, 256 threads (8 warps, warp tile 32x64)
// ================================================================
#define GLD 36

__device__ __forceinline__
void gemm_body(const float* __restrict__ A, const float* __restrict__ W,
               const float* __restrict__ bias, float* __restrict__ C,
               int roundOut)
{
    extern __shared__ float sm[];
    float* sA = sm;                    // 2 bufs x 128 x 36
    float* sB = sm + 2 * 128 * GLD;    // 2 bufs x 128 x 36

    const int M = MROWS, N = EMBED, K = EMBED;
    const int tid = threadIdx.x;
    const int lane = tid & 31, wid = tid >> 5;
    const int wm = wid & 3, wn = wid >> 2;       // 4 x 2 warps
    const int bm = blockIdx.y * 128, bn = blockIdx.x * 128;
    const int nk = K >> 5;
    (void)M;

    float acc[2][8][4];
#pragma unroll
    for (int i = 0; i < 2; i++)
#pragma unroll
        for (int j = 0; j < 8; j++)
#pragma unroll
            for (int t = 0; t < 4; t++) acc[i][j][t] = 0.f;

    auto issue = [&](int kt, int buf) {
        const float* Ag = A + (size_t)bm * K + kt * 32;
        const float* Wg = W + (size_t)bn * K + kt * 32;
        float* sa = sA + buf * 128 * GLD;
        float* sb = sB + buf * 128 * GLD;
#pragma unroll
        for (int i = 0; i < 4; i++) {
            int idx = tid + i * 256;
            int r = idx >> 3, q = idx & 7;
            cp16(sa + r * GLD + q * 4, Ag + (size_t)r * K + q * 4);
        }
#pragma unroll
        for (int i = 0; i < 4; i++) {
            int idx = tid + i * 256;
            int r = idx >> 3, q = idx & 7;
            cp16(sb + r * GLD + q * 4, Wg + (size_t)r * K + q * 4);
        }
    };

    issue(0, 0);
    cp_commit();

    for (int kt = 0; kt < nk; ++kt) {
        if (kt + 1 < nk) issue(kt + 1, (kt + 1) & 1);
        cp_commit();
        asm volatile("cp.async.wait_group 1;");
        __syncthreads();

        const float* sa = sA + (kt & 1) * 128 * GLD + (wm * 32) * GLD;
        const float* sb = sB + (kt & 1) * 128 * GLD + (wn * 64) * GLD;

#pragma unroll
        for (int kk = 0; kk < 4; kk++) {
            unsigned a[2][4], b[8][2];
            const int c0 = kk * 8 + (lane & 3);
            const int r0 = lane >> 2;
#pragma unroll
            for (int mt = 0; mt < 2; mt++) {
                const float* p = sa + (mt * 16 + r0) * GLD + c0;
                a[mt][0] = f2tf(p[0]);
                a[mt][1] = f2tf(p[8 * GLD]);
                a[mt][2] = f2tf(p[4]);
                a[mt][3] = f2tf(p[8 * GLD + 4]);
            }
#pragma unroll
            for (int nt = 0; nt < 8; nt++) {
                const float* p = sb + (nt * 8 + r0) * GLD + c0;
                b[nt][0] = f2tf(p[0]);
                b[nt][1] = f2tf(p[4]);
            }
#pragma unroll
            for (int mt = 0; mt < 2; mt++)
#pragma unroll
                for (int nt = 0; nt < 8; nt++) mma8(acc[mt][nt], a[mt], b[nt]);
        }
        __syncthreads();
    }

    // epilogue
#pragma unroll
    for (int mt = 0; mt < 2; mt++) {
        const int row = bm + wm * 32 + mt * 16 + (lane >> 2);
#pragma unroll
        for (int nt = 0; nt < 8; nt++) {
            const int col = bn + wn * 64 + nt * 8 + 2 * (lane & 3);
            const float b0 = bias[col], b1 = bias[col + 1];
            float v0 = acc[mt][nt][0] + b0, v1 = acc[mt][nt][1] + b1;
            float v2 = acc[mt][nt][2] + b0, v3 = acc[mt][nt][3] + b1;
            if (roundOut) { v0 = tf32r(v0); v1 = tf32r(v1); v2 = tf32r(v2); v3 = tf32r(v3); }
            C[(size_t)row * N + col]           = v0;
            C[(size_t)row * N + col + 1]       = v1;
            C[(size_t)(row + 8) * N + col]     = v2;
            C[(size_t)(row + 8) * N + col + 1] = v3;
        }
    }
}

__global__ __launch_bounds__(256, 2)
void gemm_qkv(const float* __restrict__ q, const float* __restrict__ Wq, const float* __restrict__ bq, float* __restrict__ qp,
              const float* __restrict__ k, const float* __restrict__ Wk, const float* __restrict__ bk, float* __restrict__ kp,
              const float* __restrict__ v, const float* __restrict__ Wv, const float* __restrict__ bv, float* __restrict__ vp)
{
    const float *A, *W, *b; float* C;
    if (blockIdx.z == 0)      { A = q; W = Wq; b = bq; C = qp; }
    else if (blockIdx.z == 1) { A = k; W = Wk; b = bk; C = kp; }
    else                      { A = v; W = Wv; b = bv; C = vp; }
    gemm_body(A, W, b, C, 1);
}

__global__ __launch_bounds__(256, 2)
void gemm_o(const float* __restrict__ A, const float* __restrict__ W,
            const float* __restrict__ b, float* __restrict__ C)
{
    gemm_body(A, W, b, C, 0);
}

// ================================================================
// Flash attention v2: 512 threads (16 warps), register softmax,
// cp.async double-buffered K + pipelined V.
// Q prescaled by 1/sqrt(EMBED)=1/32 (exact). Masks are no-ops per reference.
// ================================================================
#define LQ 68
#define LK 68
#define LV 72
#define LP 132

__global__ __launch_bounds__(512, 1)
void attn_tf32(const float* __restrict__ qp, const float* __restrict__ kp,
               const float* __restrict__ vp, float* __restrict__ op)
{
    extern __shared__ float sm[];
    float* sQ   = sm;                  // 128 x 68
    float* sK0  = sQ  + 128 * LQ;      // 128 x 68
    float* sK1  = sK0 + 128 * LK;      // 128 x 68
    float* sV   = sK1 + 128 * LK;      // 128 x 72
    float* sP   = sV  + 128 * LV;      // 128 x 132
    float* sPmx = sP  + 128 * LP;      // 512
    float* sPsm = sPmx + 512;          // 512
    float* sM   = sPsm + 512;          // 128
    float* sL   = sM + 128;            // 128
    float* sAl  = sL + 128;            // 128

    const int tid = threadIdx.x, lane = tid & 31, wid = tid >> 5;
    const int wm = wid & 3, wn = wid >> 2;          // 4 x 4 warps
    const int qd = lane & 3, r0 = lane >> 2;
    const int n = blockIdx.y >> 4, h = blockIdx.y & 15;
    const int q0 = blockIdx.x * 128;
    const size_t base = (size_t)n * LSEQ * EMBED + (size_t)h * DHEAD;

    // prologue: prefetch K[0], V[0]
#pragma unroll
    for (int i = 0; i < 4; i++) {
        int idx = tid + i * 512; int r = idx >> 4, c = idx & 15;
        cp16(sK0 + r * LK + c * 4, kp + base + (size_t)r * EMBED + c * 4);
    }
    cp_commit();
#pragma unroll
    for (int i = 0; i < 4; i++) {
        int idx = tid + i * 512; int r = idx >> 4, c = idx & 15;
        cp16(sV + r * LV + c * 4, vp + base + (size_t)r * EMBED + c * 4);
    }
    cp_commit();

    // Q load + exact prescale by 2^-5
#pragma unroll
    for (int i = 0; i < 4; i++) {
        int idx = tid + i * 512; int r = idx >> 4, c = idx & 15;
        float4 val = *(const float4*)(qp + base + (size_t)(q0 + r) * EMBED + c * 4);
        float* d = sQ + r * LQ + c * 4;
        d[0] = val.x * 0.03125f; d[1] = val.y * 0.03125f;
        d[2] = val.z * 0.03125f; d[3] = val.w * 0.03125f;
    }
    if (tid < 128) { sM[tid] = -1e30f; sL[tid] = 0.f; }

    float o[2][2][4] = {};

    for (int kb = 0; kb < NB; ++kb) {
        float* sKc = (kb & 1) ? sK1 : sK0;
        float* sKn = (kb & 1) ? sK0 : sK1;
        if (kb + 1 < NB) {
#pragma unroll
            for (int i = 0; i < 4; i++) {
                int idx = tid + i * 512; int r = idx >> 4, c = idx & 15;
                cp16(sKn + r * LK + c * 4,
                     kp + base + (size_t)((kb + 1) * 128 + r) * EMBED + c * 4);
            }
            cp_commit();
            asm volatile("cp.async.wait_group 2;");
        } else {
            asm volatile("cp.async.wait_group 1;");
        }
        __syncthreads();   // K[kb] visible; prev PV done

        // ---- S = (Q/32) K^T : warp tile 32x32, k=64 ----
        float s[2][4][4] = {};
        {
            const float* q_ = sQ + (wm * 32) * LQ;
            const float* k_ = sKc + (wn * 32) * LK;
#pragma unroll
            for (int kk = 0; kk < 8; kk++) {
                unsigned a[2][4], b[4][2];
                const int c0 = kk * 8 + qd;
#pragma unroll
                for (int mt = 0; mt < 2; mt++) {
                    const float* p = q_ + (mt * 16 + r0) * LQ + c0;
                    a[mt][0] = __float_as_uint(p[0]);
                    a[mt][1] = __float_as_uint(p[8 * LQ]);
                    a[mt][2] = __float_as_uint(p[4]);
                    a[mt][3] = __float_as_uint(p[8 * LQ + 4]);
                }
#pragma unroll
                for (int nt = 0; nt < 4; nt++) {
                    const float* p = k_ + (nt * 8 + r0) * LK + c0;
                    b[nt][0] = __float_as_uint(p[0]);
                    b[nt][1] = __float_as_uint(p[4]);
                }
#pragma unroll
                for (int mt = 0; mt < 2; mt++)
#pragma unroll
                    for (int nt = 0; nt < 4; nt++) mma8(s[mt][nt], a[mt], b[nt]);
            }
        }

        // ---- partial row max (registers + quad shuffle) ----
#pragma unroll
        for (int mt = 0; mt < 2; mt++) {
            float m0 = -1e30f, m1 = -1e30f;
#pragma unroll
            for (int nt = 0; nt < 4; nt++) {
                m0 = fmaxf(m0, fmaxf(s[mt][nt][0], s[mt][nt][1]));
                m1 = fmaxf(m1, fmaxf(s[mt][nt][2], s[mt][nt][3]));
            }
            m0 = fmaxf(m0, __shfl_xor_sync(0xffffffffu, m0, 1));
            m0 = fmaxf(m0, __shfl_xor_sync(0xffffffffu, m0, 2));
            m1 = fmaxf(m1, __shfl_xor_sync(0xffffffffu, m1, 1));
            m1 = fmaxf(m1, __shfl_xor_sync(0xffffffffu, m1, 2));
            if (qd == 0) {
                sPmx[wn * 128 + wm * 32 + mt * 16 + r0]     = m0;
                sPmx[wn * 128 + wm * 32 + mt * 16 + r0 + 8] = m1;
            }
        }
        __syncthreads();   // sync1

        if (tid < 128) {
            float mb = fmaxf(fmaxf(sPmx[tid], sPmx[128 + tid]),
                             fmaxf(sPmx[256 + tid], sPmx[384 + tid]));
            float mp = sM[tid];
            float mn = fmaxf(mp, mb);
            sAl[tid] = __expf(mp - mn);
            sM[tid]  = mn;
        }
        __syncthreads();   // sync2

        // ---- exp in registers, store P (tf32), partial sums ----
#pragma unroll
        for (int mt = 0; mt < 2; mt++) {
            const int rA = wm * 32 + mt * 16 + r0;
            const float mA = sM[rA], mB = sM[rA + 8];
            float sa = 0.f, sb = 0.f;
#pragma unroll
            for (int nt = 0; nt < 4; nt++) {
                float p0 = __expf(s[mt][nt][0] - mA), p1 = __expf(s[mt][nt][1] - mA);
                float p2 = __expf(s[mt][nt][2] - mB), p3 = __expf(s[mt][nt][3] - mB);
                sa += p0 + p1; sb += p2 + p3;
                const int c = wn * 32 + nt * 8 + 2 * qd;
                *(float2*)(sP + rA * LP + c)       = make_float2(tf32r(p0), tf32r(p1));
                *(float2*)(sP + (rA + 8) * LP + c) = make_float2(tf32r(p2), tf32r(p3));
            }
            sa += __shfl_xor_sync(0xffffffffu, sa, 1);
            sa += __shfl_xor_sync(0xffffffffu, sa, 2);
            sb += __shfl_xor_sync(0xffffffffu, sb, 1);
            sb += __shfl_xor_sync(0xffffffffu, sb, 2);
            if (qd == 0) {
                sPsm[wn * 128 + wm * 32 + mt * 16 + r0]     = sa;
                sPsm[wn * 128 + wm * 32 + mt * 16 + r0 + 8] = sb;
            }
        }
        // wait for V[kb]
        if (kb + 1 < NB) asm volatile("cp.async.wait_group 1;");
        else             asm volatile("cp.async.wait_group 0;");
        __syncthreads();   // sync3: sP, sPsm, V visible

        if (tid < 128) {
            sL[tid] = sL[tid] * sAl[tid] +
                      (sPsm[tid] + sPsm[128 + tid] + sPsm[256 + tid] + sPsm[384 + tid]);
        }

        // ---- rescale O ----
        {
            const int rA = wm * 32 + r0;
#pragma unroll
            for (int mt = 0; mt < 2; mt++) {
                const float a0 = sAl[rA + mt * 16], a1 = sAl[rA + mt * 16 + 8];
#pragma unroll
                for (int nt = 0; nt < 2; nt++) {
                    o[mt][nt][0] *= a0; o[mt][nt][1] *= a0;
                    o[mt][nt][2] *= a1; o[mt][nt][3] *= a1;
                }
            }
        }
        // ---- O += P V : warp tile 32x16, k=128 ----
        {
            const float* p_ = sP + (wm * 32) * LP;
            const float* v_ = sV + wn * 16;
#pragma unroll
            for (int kk = 0; kk < 16; kk++) {
                unsigned a[2][4], b[2][2];
                const int c0 = kk * 8 + qd;
#pragma unroll
                for (int mt = 0; mt < 2; mt++) {
                    const float* p = p_ + (mt * 16 + r0) * LP + c0;
                    a[mt][0] = __float_as_uint(p[0]);
                    a[mt][1] = __float_as_uint(p[8 * LP]);
                    a[mt][2] = __float_as_uint(p[4]);
                    a[mt][3] = __float_as_uint(p[8 * LP + 4]);
                }
#pragma unroll
                for (int nt = 0; nt < 2; nt++) {
                    const float* pv = v_ + c0 * LV + nt * 8 + r0;
                    b[nt][0] = __float_as_uint(pv[0]);
                    b[nt][1] = __float_as_uint(pv[4 * LV]);
                }
#pragma unroll
                for (int mt = 0; mt < 2; mt++)
#pragma unroll
                    for (int nt = 0; nt < 2; nt++) mma8(o[mt][nt], a[mt], b[nt]);
            }
        }
        __syncthreads();   // PV done, V buffer free
        if (kb + 1 < NB) {
#pragma unroll
            for (int i = 0; i < 4; i++) {
                int idx = tid + i * 512; int r = idx >> 4, c = idx & 15;
                cp16(sV + r * LV + c * 4,
                     vp + base + (size_t)((kb + 1) * 128 + r) * EMBED + c * 4);
            }
            cp_commit();
        }
    }

    __syncthreads();
    // ---- epilogue: normalize, store ----
#pragma unroll
    for (int mt = 0; mt < 2; mt++) {
        const int r = wm * 32 + mt * 16 + r0;
        const float inv0 = 1.f / sL[r], inv1 = 1.f / sL[r + 8];
#pragma unroll
        for (int nt = 0; nt < 2; nt++) {
            const int c = wn * 16 + nt * 8 + 2 * qd;
            const size_t g0 = base + (size_t)(q0 + r) * EMBED + c;
            const size_t g1 = base + (size_t)(q0 + r + 8) * EMBED + c;
            op[g0]     = o[mt][nt][0] * inv0;
            op[g0 + 1] = o[mt][nt][1] * inv0;
            op[g1]     = o[mt][nt][2] * inv1;
            op[g1 + 1] = o[mt][nt][3] * inv1;
        }
    }
}

// ================================================================
// launch
// ================================================================
extern "C" void kernel_launch(void* const* d_in, const int* in_sizes, int n_in,
                              void* d_out, int out_size)
{
    (void)in_sizes; (void)n_in; (void)out_size;
    const float* q  = (const float*)d_in[0];
    const float* k  = (const float*)d_in[1];
    const float* v  = (const float*)d_in[2];
    const float* Wq = (const float*)d_in[5];
    const float* bq = (const float*)d_in[6];
    const float* Wk = (const float*)d_in[7];
    const float* bk = (const float*)d_in[8];
    const float* Wv = (const float*)d_in[9];
    const float* bv = (const float*)d_in[10];
    const float* Wo = (const float*)d_in[11];
    const float* bo = (const float*)d_in[12];
    float* out = (float*)d_out;

    float *qp, *kp, *vp, *ao;
    cudaGetSymbolAddress((void**)&qp, g_qp);
    cudaGetSymbolAddress((void**)&kp, g_kp);
    cudaGetSymbolAddress((void**)&vp, g_vp);
    cudaGetSymbolAddress((void**)&ao, g_ao);

    const int gemmSmem = 2 * 128 * GLD * 2 * (int)sizeof(float);   // 73728
    const int attnSmem = (128 * LQ + 2 * 128 * LK + 128 * LV + 128 * LP
                          + 512 + 512 + 384) * (int)sizeof(float); // 214528
    static int inited = 0;
    if (!inited) {
        cudaFuncSetAttribute(gemm_qkv, cudaFuncAttributeMaxDynamicSharedMemorySize, gemmSmem);
        cudaFuncSetAttribute(gemm_o,   cudaFuncAttributeMaxDynamicSharedMemorySize, gemmSmem);
        cudaFuncSetAttribute(attn_tf32, cudaFuncAttributeMaxDynamicSharedMemorySize, attnSmem);
        inited = 1;
    }

    dim3 gg(EMBED / 128, MROWS / 128, 3);  // merged QKV: (8, 64, 3)
    dim3 go(EMBED / 128, MROWS / 128);     // (8, 64)
    dim3 ga(LSEQ / 128, NBATCH * HEADS);   // (16, 64)

    gemm_qkv<<<gg, 256, gemmSmem>>>(q, Wq, bq, qp, k, Wk, bk, kp, v, Wv, bv, vp);
    attn_tf32<<<ga, 512, attnSmem>>>(qp, kp, vp, ao);
    gemm_o<<<go, 256, gemmSmem>>>(ao, Wo, bo, out);
}

// round 4
// speedup vs baseline: 1.3928x; 1.0759x over previous
#include <cuda_runtime.h>
#include <cstdint>
#include <cstddef>

#define EMBED 1024
#define HEADS 16
#define DHEAD 64
#define NBATCH 4
#define LSEQ 2048
#define MROWS (NBATCH * LSEQ)   // 8192
#define NB (LSEQ / 128)         // 16

// ---------------- scratch (static device globals; no allocation) ----------------
__device__ __align__(256) float g_qp[(size_t)MROWS * EMBED];
__device__ __align__(256) float g_kp[(size_t)MROWS * EMBED];
__device__ __align__(256) float g_vp[(size_t)MROWS * EMBED];
__device__ __align__(256) float g_ao[(size_t)MROWS * EMBED];
__device__ __align__(256) float g_qr[(size_t)MROWS * EMBED];
__device__ __align__(256) float g_kr[(size_t)MROWS * EMBED];
__device__ __align__(256) float g_vr[(size_t)MROWS * EMBED];
__device__ __align__(256) float g_wq[(size_t)EMBED * EMBED];
__device__ __align__(256) float g_wk[(size_t)EMBED * EMBED];
__device__ __align__(256) float g_wv[(size_t)EMBED * EMBED];
__device__ __align__(256) float g_wo[(size_t)EMBED * EMBED];

// ---------------- helpers ----------------
__device__ __forceinline__ unsigned f2tf(float x) {
    unsigned u;
    asm("cvt.rna.tf32.f32 %0, %1;" : "=r"(u) : "f"(x));
    return u;
}
__device__ __forceinline__ float tf32r(float x) { return __uint_as_float(f2tf(x)); }

__device__ __forceinline__ void mma8(float* c, const unsigned* a, const unsigned* b) {
    asm volatile(
        "mma.sync.aligned.m16n8k8.row.col.f32.tf32.tf32.f32 "
        "{%0,%1,%2,%3}, {%4,%5,%6,%7}, {%8,%9}, {%0,%1,%2,%3};"
        : "+f"(c[0]), "+f"(c[1]), "+f"(c[2]), "+f"(c[3])
        : "r"(a[0]), "r"(a[1]), "r"(a[2]), "r"(a[3]), "r"(b[0]), "r"(b[1]));
}

// ldmatrix x4: 4 8x8 b16 tiles; addresses supplied by thread groups of 8.
__device__ __forceinline__ void ldsm4(unsigned* r, uint32_t addr) {
    asm volatile("ldmatrix.sync.aligned.m8n8.x4.shared.b16 {%0,%1,%2,%3}, [%4];"
        : "=r"(r[0]), "=r"(r[1]), "=r"(r[2]), "=r"(r[3]) : "r"(addr));
}

__device__ __forceinline__ void cp16(void* sdst, const void* gsrc) {
    unsigned s = (unsigned)__cvta_generic_to_shared(sdst);
    asm volatile("cp.async.cg.shared.global [%0], [%1], 16;" :: "r"(s), "l"(gsrc));
}
__device__ __forceinline__ void cp_commit() { asm volatile("cp.async.commit_group;"); }
__device__ __forceinline__ uint32_t smem_u32(const void* p) {
    return (uint32_t)__cvta_generic_to_shared(p);
}

// ================================================================
// pre-round: rna-round q,k,v and the 4 weight matrices to tf32
// ================================================================
__global__ void preround(const float4* __restrict__ s0, const float4* __restrict__ s1,
                         const float4* __restrict__ s2, const float4* __restrict__ s3,
                         const float4* __restrict__ s4, const float4* __restrict__ s5,
                         const float4* __restrict__ s6,
                         float4* __restrict__ d0, float4* __restrict__ d1,
                         float4* __restrict__ d2, float4* __restrict__ d3,
                         float4* __restrict__ d4, float4* __restrict__ d5,
                         float4* __restrict__ d6)
{
    const float4* s; float4* d; int n;
    switch (blockIdx.z) {
        case 0: s = s0; d = d0; n = MROWS * EMBED / 4; break;
        case 1: s = s1; d = d1; n = MROWS * EMBED / 4; break;
        case 2: s = s2; d = d2; n = MROWS * EMBED / 4; break;
        case 3: s = s3; d = d3; n = EMBED * EMBED / 4; break;
        case 4: s = s4; d = d4; n = EMBED * EMBED / 4; break;
        case 5: s = s5; d = d5; n = EMBED * EMBED / 4; break;
        default: s = s6; d = d6; n = EMBED * EMBED / 4; break;
    }
    for (int i = blockIdx.x * blockDim.x + threadIdx.x; i < n;
         i += gridDim.x * blockDim.x) {
        float4 v = s[i];
        v.x = tf32r(v.x); v.y = tf32r(v.y); v.z = tf32r(v.z); v.w = tf32r(v.w);
        d[i] = v;
    }
}

// ================================================================
// GEMM: C[M,N] = A[M,K] @ W[N,K]^T + bias[N]   (A, W pre-rounded tf32)
// BM=BN=128, BK=32, 256 threads (8 warps, warp tile 32x64),
// cp.async double-buffered, ldmatrix fragment loads (no cvt in loop).
// ================================================================
#define GLD 36

__device__ __forceinline__
void gemm_body(const float* __restrict__ A, const float* __restrict__ W,
               const float* __restrict__ bias, float* __restrict__ C,
               int roundOut)
{
    extern __shared__ float sm[];
    float* sA = sm;                    // 2 bufs x 128 x 36
    float* sB = sm + 2 * 128 * GLD;    // 2 bufs x 128 x 36

    const int N = EMBED, K = EMBED;
    const int tid = threadIdx.x;
    const int lane = tid & 31, wid = tid >> 5;
    const int wm = wid & 3, wn = wid >> 2;       // 4 x 2 warps
    const int bm = blockIdx.y * 128, bn = blockIdx.x * 128;
    const int nk = K >> 5;

    // per-thread ldmatrix offsets (bytes)
    const uint32_t offA = ((wm * 32 + (lane & 15)) * GLD + (lane >> 4) * 4) * 4;
    const uint32_t offB = (((lane & 7) + ((lane >> 4) << 3) + wn * 64) * GLD
                           + ((lane >> 3) & 1) * 4) * 4;
    const uint32_t sAu = smem_u32(sA), sBu = smem_u32(sB);

    float acc[2][8][4];
#pragma unroll
    for (int i = 0; i < 2; i++)
#pragma unroll
        for (int j = 0; j < 8; j++)
#pragma unroll
            for (int t = 0; t < 4; t++) acc[i][j][t] = 0.f;

    auto issue = [&](int kt, int buf) {
        const float* Ag = A + (size_t)bm * K + kt * 32;
        const float* Wg = W + (size_t)bn * K + kt * 32;
        float* sa = sA + buf * 128 * GLD;
        float* sb = sB + buf * 128 * GLD;
#pragma unroll
        for (int i = 0; i < 4; i++) {
            int idx = tid + i * 256;
            int r = idx >> 3, q = idx & 7;
            cp16(sa + r * GLD + q * 4, Ag + (size_t)r * K + q * 4);
        }
#pragma unroll
        for (int i = 0; i < 4; i++) {
            int idx = tid + i * 256;
            int r = idx >> 3, q = idx & 7;
            cp16(sb + r * GLD + q * 4, Wg + (size_t)r * K + q * 4);
        }
    };

    issue(0, 0);
    cp_commit();

    for (int kt = 0; kt < nk; ++kt) {
        if (kt + 1 < nk) issue(kt + 1, (kt + 1) & 1);
        cp_commit();
        asm volatile("cp.async.wait_group 1;");
        __syncthreads();

        const uint32_t sa = sAu + (kt & 1) * 128 * GLD * 4 + offA;
        const uint32_t sb = sBu + (kt & 1) * 128 * GLD * 4 + offB;

#pragma unroll
        for (int kk = 0; kk < 4; kk++) {
            unsigned a[2][4], b[8][2];
            ldsm4(a[0], sa + kk * 32);
            ldsm4(a[1], sa + 16 * GLD * 4 + kk * 32);
#pragma unroll
            for (int g = 0; g < 4; g++) {
                unsigned t4[4];
                ldsm4(t4, sb + g * 16 * GLD * 4 + kk * 32);
                b[2 * g][0] = t4[0]; b[2 * g][1] = t4[1];
                b[2 * g + 1][0] = t4[2]; b[2 * g + 1][1] = t4[3];
            }
#pragma unroll
            for (int mt = 0; mt < 2; mt++)
#pragma unroll
                for (int nt = 0; nt < 8; nt++) mma8(acc[mt][nt], a[mt], b[nt]);
        }
        __syncthreads();
    }

    // epilogue
#pragma unroll
    for (int mt = 0; mt < 2; mt++) {
        const int row = bm + wm * 32 + mt * 16 + (lane >> 2);
#pragma unroll
        for (int nt = 0; nt < 8; nt++) {
            const int col = bn + wn * 64 + nt * 8 + 2 * (lane & 3);
            const float b0 = bias[col], b1 = bias[col + 1];
            float v0 = acc[mt][nt][0] + b0, v1 = acc[mt][nt][1] + b1;
            float v2 = acc[mt][nt][2] + b0, v3 = acc[mt][nt][3] + b1;
            if (roundOut) { v0 = tf32r(v0); v1 = tf32r(v1); v2 = tf32r(v2); v3 = tf32r(v3); }
            C[(size_t)row * N + col]           = v0;
            C[(size_t)row * N + col + 1]       = v1;
            C[(size_t)(row + 8) * N + col]     = v2;
            C[(size_t)(row + 8) * N + col + 1] = v3;
        }
    }
}

__global__ __launch_bounds__(256, 2)
void gemm_qkv(const float* __restrict__ q, const float* __restrict__ Wq, const float* __restrict__ bq, float* __restrict__ qp,
              const float* __restrict__ k, const float* __restrict__ Wk, const float* __restrict__ bk, float* __restrict__ kp,
              const float* __restrict__ v, const float* __restrict__ Wv, const float* __restrict__ bv, float* __restrict__ vp)
{
    const float *A, *W, *b; float* C;
    if (blockIdx.z == 0)      { A = q; W = Wq; b = bq; C = qp; }
    else if (blockIdx.z == 1) { A = k; W = Wk; b = bk; C = kp; }
    else                      { A = v; W = Wv; b = bv; C = vp; }
    gemm_body(A, W, b, C, 1);
}

__global__ __launch_bounds__(256, 2)
void gemm_o(const float* __restrict__ A, const float* __restrict__ W,
            const float* __restrict__ b, float* __restrict__ C)
{
    gemm_body(A, W, b, C, 0);
}

// ================================================================
// Flash attention: 512 threads (16 warps), register softmax,
// cp.async double-buffered K + pipelined V, ldmatrix fragment loads.
// Q prescaled by 1/32 (exact). Masks are no-ops per reference.
// Output rounded to tf32 (feeds raw into gemm_o).
// ================================================================
#define LQ 68
#define LK 68
#define LV 72
#define LP 132

__global__ __launch_bounds__(512, 1)
void attn_tf32(const float* __restrict__ qp, const float* __restrict__ kp,
               const float* __restrict__ vp, float* __restrict__ op)
{
    extern __shared__ float sm[];
    float* sQ   = sm;                  // 128 x 68
    float* sK0  = sQ  + 128 * LQ;      // 128 x 68
    float* sK1  = sK0 + 128 * LK;      // 128 x 68
    float* sV   = sK1 + 128 * LK;      // 128 x 72
    float* sP   = sV  + 128 * LV;      // 128 x 132
    float* sPmx = sP  + 128 * LP;      // 512
    float* sPsm = sPmx + 512;          // 512
    float* sM   = sPsm + 512;          // 128
    float* sL   = sM + 128;            // 128
    float* sAl  = sL + 128;            // 128

    const int tid = threadIdx.x, lane = tid & 31, wid = tid >> 5;
    const int wm = wid & 3, wn = wid >> 2;          // 4 x 4 warps
    const int qd = lane & 3, r0 = lane >> 2;
    const int n = blockIdx.y >> 4, h = blockIdx.y & 15;
    const int q0 = blockIdx.x * 128;
    const size_t base = (size_t)n * LSEQ * EMBED + (size_t)h * DHEAD;

    // ldmatrix per-thread offsets (bytes)
    const uint32_t offQ = ((wm * 32 + (lane & 15)) * LQ + (lane >> 4) * 4) * 4;
    const uint32_t offK = (((lane & 7) + ((lane >> 4) << 3) + wn * 32) * LK
                           + ((lane >> 3) & 1) * 4) * 4;
    const uint32_t offP = ((wm * 32 + (lane & 15)) * LP + (lane >> 4) * 4) * 4;
    const uint32_t sQa = smem_u32(sQ) + offQ;
    const uint32_t sPa = smem_u32(sP) + offP;
    const uint32_t sK0a = smem_u32(sK0) + offK;
    const uint32_t sK1a = smem_u32(sK1) + offK;

    // prologue: prefetch K[0], V[0]
#pragma unroll
    for (int i = 0; i < 4; i++) {
        int idx = tid + i * 512; int r = idx >> 4, c = idx & 15;
        cp16(sK0 + r * LK + c * 4, kp + base + (size_t)r * EMBED + c * 4);
    }
    cp_commit();
#pragma unroll
    for (int i = 0; i < 4; i++) {
        int idx = tid + i * 512; int r = idx >> 4, c = idx & 15;
        cp16(sV + r * LV + c * 4, vp + base + (size_t)r * EMBED + c * 4);
    }
    cp_commit();

    // Q load + exact prescale by 2^-5
#pragma unroll
    for (int i = 0; i < 4; i++) {
        int idx = tid + i * 512; int r = idx >> 4, c = idx & 15;
        float4 val = *(const float4*)(qp + base + (size_t)(q0 + r) * EMBED + c * 4);
        float* d = sQ + r * LQ + c * 4;
        d[0] = val.x * 0.03125f; d[1] = val.y * 0.03125f;
        d[2] = val.z * 0.03125f; d[3] = val.w * 0.03125f;
    }
    if (tid < 128) { sM[tid] = -1e30f; sL[tid] = 0.f; }

    float o[2][2][4] = {};

    for (int kb = 0; kb < NB; ++kb) {
        const uint32_t sKa = (kb & 1) ? sK1a : sK0a;
        float* sKn = (kb & 1) ? sK0 : sK1;
        if (kb + 1 < NB) {
#pragma unroll
            for (int i = 0; i < 4; i++) {
                int idx = tid + i * 512; int r = idx >> 4, c = idx & 15;
                cp16(sKn + r * LK + c * 4,
                     kp + base + (size_t)((kb + 1) * 128 + r) * EMBED + c * 4);
            }
            cp_commit();
            asm volatile("cp.async.wait_group 2;");
        } else {
            asm volatile("cp.async.wait_group 1;");
        }
        __syncthreads();   // K[kb] visible; prev PV done

        // ---- S = (Q/32) K^T : warp tile 32x32, k=64, ldmatrix loads ----
        float s[2][4][4] = {};
#pragma unroll
        for (int kk = 0; kk < 8; kk++) {
            unsigned a[2][4], b[4][2];
            ldsm4(a[0], sQa + kk * 32);
            ldsm4(a[1], sQa + 16 * LQ * 4 + kk * 32);
#pragma unroll
            for (int g = 0; g < 2; g++) {
                unsigned t4[4];
                ldsm4(t4, sKa + g * 16 * LK * 4 + kk * 32);
                b[2 * g][0] = t4[0]; b[2 * g][1] = t4[1];
                b[2 * g + 1][0] = t4[2]; b[2 * g + 1][1] = t4[3];
            }
#pragma unroll
            for (int mt = 0; mt < 2; mt++)
#pragma unroll
                for (int nt = 0; nt < 4; nt++) mma8(s[mt][nt], a[mt], b[nt]);
        }

        // ---- partial row max (registers + quad shuffle) ----
#pragma unroll
        for (int mt = 0; mt < 2; mt++) {
            float m0 = -1e30f, m1 = -1e30f;
#pragma unroll
            for (int nt = 0; nt < 4; nt++) {
                m0 = fmaxf(m0, fmaxf(s[mt][nt][0], s[mt][nt][1]));
                m1 = fmaxf(m1, fmaxf(s[mt][nt][2], s[mt][nt][3]));
            }
            m0 = fmaxf(m0, __shfl_xor_sync(0xffffffffu, m0, 1));
            m0 = fmaxf(m0, __shfl_xor_sync(0xffffffffu, m0, 2));
            m1 = fmaxf(m1, __shfl_xor_sync(0xffffffffu, m1, 1));
            m1 = fmaxf(m1, __shfl_xor_sync(0xffffffffu, m1, 2));
            if (qd == 0) {
                sPmx[wn * 128 + wm * 32 + mt * 16 + r0]     = m0;
                sPmx[wn * 128 + wm * 32 + mt * 16 + r0 + 8] = m1;
            }
        }
        __syncthreads();

        if (tid < 128) {
            float mb = fmaxf(fmaxf(sPmx[tid], sPmx[128 + tid]),
                             fmaxf(sPmx[256 + tid], sPmx[384 + tid]));
            float mp = sM[tid];
            float mn = fmaxf(mp, mb);
            sAl[tid] = __expf(mp - mn);
            sM[tid]  = mn;
        }
        __syncthreads();

        // ---- exp in registers, store P (tf32), partial sums ----
#pragma unroll
        for (int mt = 0; mt < 2; mt++) {
            const int rA = wm * 32 + mt * 16 + r0;
            const float mA = sM[rA], mB = sM[rA + 8];
            float sa = 0.f, sb = 0.f;
#pragma unroll
            for (int nt = 0; nt < 4; nt++) {
                float p0 = __expf(s[mt][nt][0] - mA), p1 = __expf(s[mt][nt][1] - mA);
                float p2 = __expf(s[mt][nt][2] - mB), p3 = __expf(s[mt][nt][3] - mB);
                sa += p0 + p1; sb += p2 + p3;
                const int c = wn * 32 + nt * 8 + 2 * qd;
                *(float2*)(sP + rA * LP + c)       = make_float2(tf32r(p0), tf32r(p1));
                *(float2*)(sP + (rA + 8) * LP + c) = make_float2(tf32r(p2), tf32r(p3));
            }
            sa += __shfl_xor_sync(0xffffffffu, sa, 1);
            sa += __shfl_xor_sync(0xffffffffu, sa, 2);
            sb += __shfl_xor_sync(0xffffffffu, sb, 1);
            sb += __shfl_xor_sync(0xffffffffu, sb, 2);
            if (qd == 0) {
                sPsm[wn * 128 + wm * 32 + mt * 16 + r0]     = sa;
                sPsm[wn * 128 + wm * 32 + mt * 16 + r0 + 8] = sb;
            }
        }
        // wait for V[kb]
        if (kb + 1 < NB) asm volatile("cp.async.wait_group 1;");
        else             asm volatile("cp.async.wait_group 0;");
        __syncthreads();   // sP, sPsm, V visible

        if (tid < 128) {
            sL[tid] = sL[tid] * sAl[tid] +
                      (sPsm[tid] + sPsm[128 + tid] + sPsm[256 + tid] + sPsm[384 + tid]);
        }

        // ---- rescale O ----
        {
            const int rA = wm * 32 + r0;
#pragma unroll
            for (int mt = 0; mt < 2; mt++) {
                const float a0 = sAl[rA + mt * 16], a1 = sAl[rA + mt * 16 + 8];
#pragma unroll
                for (int nt = 0; nt < 2; nt++) {
                    o[mt][nt][0] *= a0; o[mt][nt][1] *= a0;
                    o[mt][nt][2] *= a1; o[mt][nt][3] *= a1;
                }
            }
        }
        // ---- O += P V : warp tile 32x16, k=128, ldmatrix for P ----
        {
            const float* v_ = sV + wn * 16;
#pragma unroll
            for (int kk = 0; kk < 16; kk++) {
                unsigned a[2][4], b[2][2];
                ldsm4(a[0], sPa + kk * 32);
                ldsm4(a[1], sPa + 16 * LP * 4 + kk * 32);
                const int c0 = kk * 8 + qd;
#pragma unroll
                for (int nt = 0; nt < 2; nt++) {
                    const float* pv = v_ + c0 * LV + nt * 8 + r0;
                    b[nt][0] = __float_as_uint(pv[0]);
                    b[nt][1] = __float_as_uint(pv[4 * LV]);
                }
#pragma unroll
                for (int mt = 0; mt < 2; mt++)
#pragma unroll
                    for (int nt = 0; nt < 2; nt++) mma8(o[mt][nt], a[mt], b[nt]);
            }
        }
        __syncthreads();   // PV done, V buffer free
        if (kb + 1 < NB) {
#pragma unroll
            for (int i = 0; i < 4; i++) {
                int idx = tid + i * 512; int r = idx >> 4, c = idx & 15;
                cp16(sV + r * LV + c * 4,
                     vp + base + (size_t)((kb + 1) * 128 + r) * EMBED + c * 4);
            }
            cp_commit();
        }
    }

    __syncthreads();
    // ---- epilogue: normalize, round to tf32, store ----
#pragma unroll
    for (int mt = 0; mt < 2; mt++) {
        const int r = wm * 32 + mt * 16 + r0;
        const float inv0 = 1.f / sL[r], inv1 = 1.f / sL[r + 8];
#pragma unroll
        for (int nt = 0; nt < 2; nt++) {
            const int c = wn * 16 + nt * 8 + 2 * qd;
            const size_t g0 = base + (size_t)(q0 + r) * EMBED + c;
            const size_t g1 = base + (size_t)(q0 + r + 8) * EMBED + c;
            op[g0]     = tf32r(o[mt][nt][0] * inv0);
            op[g0 + 1] = tf32r(o[mt][nt][1] * inv0);
            op[g1]     = tf32r(o[mt][nt][2] * inv1);
            op[g1 + 1] = tf32r(o[mt][nt][3] * inv1);
        }
    }
}

// ================================================================
// launch
// ================================================================
extern "C" void kernel_launch(void* const* d_in, const int* in_sizes, int n_in,
                              void* d_out, int out_size)
{
    (void)in_sizes; (void)n_in; (void)out_size;
    const float* q  = (const float*)d_in[0];
    const float* k  = (const float*)d_in[1];
    const float* v  = (const float*)d_in[2];
    const float* Wq = (const float*)d_in[5];
    const float* bq = (const float*)d_in[6];
    const float* Wk = (const float*)d_in[7];
    const float* bk = (const float*)d_in[8];
    const float* Wv = (const float*)d_in[9];
    const float* bv = (const float*)d_in[10];
    const float* Wo = (const float*)d_in[11];
    const float* bo = (const float*)d_in[12];
    float* out = (float*)d_out;

    float *qp, *kp, *vp, *ao, *qr, *kr, *vr, *wq, *wk, *wv, *wo;
    cudaGetSymbolAddress((void**)&qp, g_qp);
    cudaGetSymbolAddress((void**)&kp, g_kp);
    cudaGetSymbolAddress((void**)&vp, g_vp);
    cudaGetSymbolAddress((void**)&ao, g_ao);
    cudaGetSymbolAddress((void**)&qr, g_qr);
    cudaGetSymbolAddress((void**)&kr, g_kr);
    cudaGetSymbolAddress((void**)&vr, g_vr);
    cudaGetSymbolAddress((void**)&wq, g_wq);
    cudaGetSymbolAddress((void**)&wk, g_wk);
    cudaGetSymbolAddress((void**)&wv, g_wv);
    cudaGetSymbolAddress((void**)&wo, g_wo);

    const int gemmSmem = 2 * 128 * GLD * 2 * (int)sizeof(float);   // 73728
    const int attnSmem = (128 * LQ + 2 * 128 * LK + 128 * LV + 128 * LP
                          + 512 + 512 + 384) * (int)sizeof(float); // 214528
    static int inited = 0;
    if (!inited) {
        cudaFuncSetAttribute(gemm_qkv, cudaFuncAttributeMaxDynamicSharedMemorySize, gemmSmem);
        cudaFuncSetAttribute(gemm_o,   cudaFuncAttributeMaxDynamicSharedMemorySize, gemmSmem);
        cudaFuncSetAttribute(attn_tf32, cudaFuncAttributeMaxDynamicSharedMemorySize, attnSmem);
        inited = 1;
    }

    dim3 gpr(2048, 1, 7);
    dim3 gg(EMBED / 128, MROWS / 128, 3);  // merged QKV: (8, 64, 3)
    dim3 go(EMBED / 128, MROWS / 128);     // (8, 64)
    dim3 ga(LSEQ / 128, NBATCH * HEADS);   // (16, 64)

    preround<<<gpr, 256>>>((const float4*)q, (const float4*)k, (const float4*)v,
                           (const float4*)Wq, (const float4*)Wk, (const float4*)Wv,
                           (const float4*)Wo,
                           (float4*)qr, (float4*)kr, (float4*)vr,
                           (float4*)wq, (float4*)wk, (float4*)wv, (float4*)wo);
    gemm_qkv<<<gg, 256, gemmSmem>>>(qr, wq, bq, qp, kr, wk, bk, kp, vr, wv, bv, vp);
    attn_tf32<<<ga, 512, attnSmem>>>(qp, kp, vp, ao);
    gemm_o<<<go, 256, gemmSmem>>>(ao, wo, bo, out);
}